// round 3
// baseline (speedup 1.0000x reference)
#include <cuda_runtime.h>
#include <math.h>

// ---------------------------------------------------------------------------
// Problem: N=3072 points. For every pair (i,j):
//   mask      = batch_eq & block_le & (forcekeep|keep_coarse) & (forcekeep|keepr)
//   dxyz_m    = mask ? xyz[i]-xyz[j] : 0                       (N,N,3) f32
//   buckets   = mask ? sum_d MUL[d]*(8 + bucket(dxyz_d)) : 0   (N,N)   i32->f32
//   dscanid   = mask ? block[j]/2 - block[i]/2 : 0             (N,N)   i32->f32
//   mask                                                        (N,N)   bool->f32
// Output assumed: float32, sections concatenated in return order.
// ---------------------------------------------------------------------------

#define MAXN 8192
__device__ float4 g_P[MAXN];   // {x, y, z, packed_meta}

// packed_meta bits: [0:3) batch, [3:6) block, [6:9) c0, [9:12) c1, [12:15) c2,
//                   [15:20) xy_coarse0, [20:25) xy_coarse1
__global__ void pack_kernel(const float* __restrict__ xyz,
                            const int*   __restrict__ grid, int N) {
    int i = blockIdx.x * blockDim.x + threadIdx.x;
    if (i >= N) return;
    float x = xyz[3*i+0], y = xyz[3*i+1], z = xyz[3*i+2];
    int batch = grid[5*i+0], blk = grid[5*i+1];
    int c0 = grid[5*i+2], c1 = grid[5*i+3], c2 = grid[5*i+4];
    // xy_coarse = ceil(xyz[:, :2] / 3.0)  — pin IEEE division (fast-math safe)
    int xc0 = (int)ceilf(__fdiv_rn(x, 3.0f));
    int xc1 = (int)ceilf(__fdiv_rn(y, 3.0f));
    unsigned meta = (unsigned)(batch & 7)
                  | ((unsigned)(blk   & 7)  << 3)
                  | ((unsigned)(c0    & 7)  << 6)
                  | ((unsigned)(c1    & 7)  << 9)
                  | ((unsigned)(c2    & 7)  << 12)
                  | ((unsigned)(xc0   & 31) << 15)
                  | ((unsigned)(xc1   & 31) << 20);
    g_P[i] = make_float4(x, y, z, __uint_as_float(meta));
}

// bucket_base without the +BETA offset: returns integer-valued float v,
// reference value is BETA + v.
__device__ __forceinline__ float bucket_v(float d) {
    float x  = d * 2.0f;            // x / RES, RES = 0.5 (exact)
    float xa = fabsf(x);
    if (xa <= 2.0f) {
        return rintf(x);            // round-half-even == jnp.round
    } else {
        // log_ratio = log(xa/2)/log(8);  sup = min(round(2 - 6*lr), 8); signed
        float lr  = logf(xa * 0.5f) * 0.48089834696298783f; // 1/ln(8)
        float sup = fminf(rintf(2.0f - 6.0f * lr), 8.0f);
        return (x > 0.0f) ? sup : -sup;
    }
}

__global__ __launch_bounds__(256)
void pair_kernel(float* __restrict__ out, int N) {
    int i  = blockIdx.y;
    int j0 = (blockIdx.x * blockDim.x + threadIdx.x) * 4;
    if (j0 >= N) return;

    float4 pi = g_P[i];
    unsigned mi = __float_as_uint(pi.w);
    int bi  = (mi >> 3)  & 7;
    int ci0 = (mi >> 6)  & 7, ci1 = (mi >> 9) & 7, ci2 = (mi >> 12) & 7;
    int xi0 = (mi >> 15) & 31, xi1 = (mi >> 20) & 31;
    int si  = bi >> 1;   // scanid_i

    float dxs[12];
    float bks[4], dss[4], mks[4];

    int nvalid = (N - j0 < 4) ? (N - j0) : 4;

#pragma unroll
    for (int t = 0; t < 4; t++) {
        int j = j0 + t;
        if (t >= nvalid) { dxs[3*t]=dxs[3*t+1]=dxs[3*t+2]=0.f; bks[t]=dss[t]=mks[t]=0.f; continue; }
        float4 pj = g_P[j];
        unsigned mj = __float_as_uint(pj.w);

        bool batch_eq = ((mi ^ mj) & 7u) == 0u;
        int  bj       = (mj >> 3) & 7;
        bool block_le = bi <= bj;

        int dc0 = ci0 - (int)((mj >> 6)  & 7);
        int dc1 = ci1 - (int)((mj >> 9)  & 7);
        int dc2 = ci2 - (int)((mj >> 12) & 7);
        bool coord_adj = (abs(dc0) <= 1) & (abs(dc1) <= 1) & (abs(dc2) <= 1);
        bool forcekeep = coord_adj & (bi == bj);

        int e0 = xi0 - (int)((mj >> 15) & 31);
        int e1 = xi1 - (int)((mj >> 20) & 31);
        bool keep_coarse = (abs(e0) <= 1) & (abs(e1) <= 1);

        float dx = pi.x - pj.x, dy = pi.y - pj.y, dz = pi.z - pj.z;
        bool keepr = (dx*dx + dy*dy + dz*dz) <= 9.0f;

        bool mask = batch_eq & block_le & (forcekeep | keep_coarse)
                                        & (forcekeep | keepr);

        float fdx = mask ? dx : 0.0f;
        float fdy = mask ? dy : 0.0f;
        float fdz = mask ? dz : 0.0f;

        int b = 0, ds = 0;
        if (mask) {
            // MUL = [289, 17, 1]; exact integer arithmetic
            b = 289 * (8 + (int)bucket_v(dx))
              +  17 * (8 + (int)bucket_v(dy))
              +        (8 + (int)bucket_v(dz));
            ds = (bj >> 1) - si;
        }

        dxs[3*t+0] = fdx; dxs[3*t+1] = fdy; dxs[3*t+2] = fdz;
        bks[t] = (float)b;
        dss[t] = (float)ds;
        mks[t] = mask ? 1.0f : 0.0f;
    }

    size_t NN  = (size_t)N * (size_t)N;
    size_t row = (size_t)i * (size_t)N + (size_t)j0;

    if (nvalid == 4) {
        // dxyz section: 12 consecutive floats at (i*N + j0)*3 -> 3 float4 stores
        float4* dp = reinterpret_cast<float4*>(out + row * 3);
        dp[0] = make_float4(dxs[0], dxs[1], dxs[2],  dxs[3]);
        dp[1] = make_float4(dxs[4], dxs[5], dxs[6],  dxs[7]);
        dp[2] = make_float4(dxs[8], dxs[9], dxs[10], dxs[11]);
        *reinterpret_cast<float4*>(out + 3*NN + row) = make_float4(bks[0], bks[1], bks[2], bks[3]);
        *reinterpret_cast<float4*>(out + 4*NN + row) = make_float4(dss[0], dss[1], dss[2], dss[3]);
        *reinterpret_cast<float4*>(out + 5*NN + row) = make_float4(mks[0], mks[1], mks[2], mks[3]);
    } else {
        for (int t = 0; t < nvalid; t++) {
            out[(row + t)*3 + 0] = dxs[3*t+0];
            out[(row + t)*3 + 1] = dxs[3*t+1];
            out[(row + t)*3 + 2] = dxs[3*t+2];
            out[3*NN + row + t] = bks[t];
            out[4*NN + row + t] = dss[t];
            out[5*NN + row + t] = mks[t];
        }
    }
}

extern "C" void kernel_launch(void* const* d_in, const int* in_sizes, int n_in,
                              void* d_out, int out_size) {
    const float* xyz  = (const float*)d_in[0];
    const int*   grid = (const int*)d_in[1];
    int N = in_sizes[0] / 3;
    float* out = (float*)d_out;

    pack_kernel<<<(N + 255) / 256, 256>>>(xyz, grid, N);

    dim3 g((N + 1023) / 1024, N);
    pair_kernel<<<g, 256>>>(out, N);
}